// round 11
// baseline (speedup 1.0000x reference)
#include <cuda_runtime.h>

// Quanvolution quantum filter — closed-form Heisenberg-picture evaluation.
// 4 patch-pairs (8 patches) per thread: the 18 layer-1 coefficient products
// and parameter trig are computed ONCE per thread and amortized across all
// 4 packed-f32x2 polynomial evaluations. Block owns 512 consecutive pairs
// (4 chunks of 128), keeping warp loads coalesced and L2-local.
// Streaming load/store hints: every input byte read once, output written once.

#define BATCH   8192
#define NPAIR   (BATCH * 98)        // 802816 = 1568 * 512

typedef unsigned long long u64;

__device__ __forceinline__ u64 pk2(float lo, float hi) {
    u64 r; asm("mov.b64 %0, {%1, %2};" : "=l"(r) : "f"(lo), "f"(hi)); return r;
}
__device__ __forceinline__ u64 bc2(float v) { return pk2(v, v); }
__device__ __forceinline__ u64 mul2(u64 a, u64 b) {
    u64 r; asm("mul.rn.f32x2 %0, %1, %2;" : "=l"(r) : "l"(a), "l"(b)); return r;
}
__device__ __forceinline__ u64 fma2(u64 a, u64 b, u64 c) {
    u64 r; asm("fma.rn.f32x2 %0, %1, %2, %3;" : "=l"(r) : "l"(a), "l"(b), "l"(c)); return r;
}
__device__ __forceinline__ void upk2(u64 v, float& lo, float& hi) {
    asm("mov.b64 {%0, %1}, %2;" : "=f"(lo), "=f"(hi) : "l"(v));
}

__global__ __launch_bounds__(128)
void quanv11_kernel(const float* __restrict__ x,
                    const float* __restrict__ params,
                    float* __restrict__ out)
{
    // ---- per-thread coefficient computation (once, amortized over 4 pairs) ----
    float4 Pv = __ldg(reinterpret_cast<const float4*>(params));       // layer-0
    float4 Qv = __ldg(reinterpret_cast<const float4*>(params) + 1);   // layer-1

    float c0, s0, c1, s1, c2, s2, c3, s3;
    __sincosf(Qv.x, &s0, &c0);
    __sincosf(Qv.y, &s1, &c1);
    __sincosf(Qv.z, &s2, &c2);
    __sincosf(Qv.w, &s3, &c3);

    float c01 = c0 * c1, s01 = s0 * s1, c0s1 = c0 * s1, s0c1 = s0 * c1;
    float c23 = c2 * c3, s23 = s2 * s3, c2s3 = c2 * s3, s2c3 = s2 * c3;

    // Scalar coefficients in registers; packed (broadcast) on use — the
    // bc2 pack is a cheap ALU op and keeps register pressure down.
    float k0  =  c1 * c23,    k1  = -c1 * c2s3;
    float k2  = -s1 * c23,    k3  = -s1 * s23;
    float k4  =  c01,         k5  =  s01;
    float k6  =  c01 * c2,    k7  = -c0s1 * c2;
    float k8  = -s0c1 * c2,   k9  = -s01 * s2;
    float k10 =  c01 * c23,   k11 = -c01 * s2c3;
    float k12 =  s01 * c23,   k13 =  s0c1 * c2s3;
    float k14 =  c0s1 * s2c3, k15 = -s0c1 * s23;
    float k16 = -c0s1 * s23,  k17 =  s01 * s23;

    int qbase = blockIdx.x * 512 + threadIdx.x;

    #pragma unroll
    for (int it = 0; it < 4; ++it) {
        int q  = qbase + it * 128;
        int b  = q / 98;
        int pp = q - b * 98;
        int r  = pp / 7;
        int j  = pp - r * 7;

        const float* img = x + b * 784 + (2 * r) * 28 + 4 * j;
        float4 top = __ldcs(reinterpret_cast<const float4*>(img));
        float4 bot = __ldcs(reinterpret_cast<const float4*>(img + 28));

        // Full angles a_v = x_v + params[0][v]; Z = cos a, X = sin a.
        float zA0, xA0, zA1, xA1, zA2, xA2, zA3, xA3;   // patch A (lo lane)
        float zB0, xB0, zB1, xB1, zB2, xB2, zB3, xB3;   // patch B (hi lane)
        __sincosf(top.x + Pv.x, &xA0, &zA0);
        __sincosf(top.y + Pv.y, &xA1, &zA1);
        __sincosf(bot.x + Pv.z, &xA2, &zA2);
        __sincosf(bot.y + Pv.w, &xA3, &zA3);
        __sincosf(top.z + Pv.x, &xB0, &zB0);
        __sincosf(top.w + Pv.y, &xB1, &zB1);
        __sincosf(bot.z + Pv.z, &xB2, &zB2);
        __sincosf(bot.w + Pv.w, &xB3, &zB3);

        u64 Z0 = pk2(zA0, zB0), X0 = pk2(xA0, xB0);
        u64 Z1 = pk2(zA1, zB1), X1 = pk2(xA1, xB1);
        u64 Z2 = pk2(zA2, zB2), X2 = pk2(xA2, xB2);
        u64 Z3 = pk2(zA3, zB3), X3 = pk2(xA3, xB3);

        u64 zz01 = mul2(Z0, Z1), zz02 = mul2(Z0, Z2), zz03 = mul2(Z0, Z3);
        u64 zz13 = mul2(Z1, Z3), zz23 = mul2(Z2, Z3);
        u64 xx01 = mul2(X0, X1), xx02 = mul2(X0, X2), xx03 = mul2(X0, X3);
        u64 xx12 = mul2(X1, X2), xx13 = mul2(X1, X3), xx23 = mul2(X2, X3);
        u64 zx23 = mul2(Z2, X3);

        // E[Z_0] = k0*z0z1z3 + k1*x0x1z2x3 + k2*x1x2z3 + k3*x0
        u64 e0 = mul2(bc2(k0), mul2(zz01, Z3));
        e0 = fma2(bc2(k1), mul2(xx01, zx23), e0);
        e0 = fma2(bc2(k2), mul2(xx12, Z3), e0);
        e0 = fma2(bc2(k3), X0, e0);

        // E[Z_1] = k4*z0z2z3 + k5*x0x2
        u64 e1 = mul2(bc2(k4), mul2(Z0, zz23));
        e1 = fma2(bc2(k5), xx02, e1);

        // E[Z_2] = k6*z1z3 + k7*z0x1x2z3 + k8*x0x1z2 + k9*x0x3
        u64 e2 = mul2(bc2(k6), zz13);
        e2 = fma2(bc2(k7), mul2(xx12, zz03), e2);
        e2 = fma2(bc2(k8), mul2(xx01, Z2), e2);
        e2 = fma2(bc2(k9), xx03, e2);

        // E[Z_3] = k10*z0z2 + k11*z1x2x3 + k12*x0x2z3 + k13*z2x3
        //        + k14*z0x1x3 + k15*z0z1x2 + k16*x0z1z2z3 + k17*x1
        u64 e3 = mul2(bc2(k10), zz02);
        e3 = fma2(bc2(k11), mul2(Z1, xx23), e3);
        e3 = fma2(bc2(k12), mul2(xx02, Z3), e3);
        e3 = fma2(bc2(k13), zx23, e3);
        e3 = fma2(bc2(k14), mul2(Z0, xx13), e3);
        e3 = fma2(bc2(k15), mul2(zz01, X2), e3);
        e3 = fma2(bc2(k16), mul2(mul2(zz13, Z2), X0), e3);
        e3 = fma2(bc2(k17), X1, e3);

        float4 o0, o1;
        upk2(e0, o0.x, o1.x);
        upk2(e1, o0.y, o1.y);
        upk2(e2, o0.z, o1.z);
        upk2(e3, o0.w, o1.w);

        float4* dst = reinterpret_cast<float4*>(out) + 2 * q;
        __stcs(dst,     o0);
        __stcs(dst + 1, o1);
    }
}

extern "C" void kernel_launch(void* const* d_in, const int* in_sizes, int n_in,
                              void* d_out, int out_size)
{
    const float* x      = (const float*)d_in[0];   // (8192,1,28,28) float32
    const float* params = (const float*)d_in[1];   // (2,4) float32
    float* out          = (float*)d_out;           // (8192, 784) float32

    (void)in_sizes; (void)n_in; (void)out_size;

    const int threads = 128;
    const int blocks  = NPAIR / (threads * 4);     // 1568, exact
    quanv11_kernel<<<blocks, threads>>>(x, params, out);
}

// round 12
// speedup vs baseline: 1.0025x; 1.0025x over previous
#include <cuda_runtime.h>

// Quanvolution quantum filter — closed-form Heisenberg evaluation, SCALAR.
// One thread = one patch; maximize occupancy/TLP (the packed variants all
// plateaued at ~46% issue). Coefficients factored into 12 constants
// (grouped by wire-0/1 trig factors, signs folded into FFMA negation),
// so constants+shifts = 16 floats = 4x LDS.128 per thread.

#define BATCH   8192
#define NPATCH  196
#define NTOT    (BATCH * NPATCH)    // 1605632 = 12544 * 128

__global__ __launch_bounds__(128, 13)
void quanv12_kernel(const float* __restrict__ x,
                    const float* __restrict__ params,
                    float* __restrict__ out)
{
    // Ks layout: [c01,s01,c0s1,s0c1 | c23,s23,c2s3,s2c3 | c1,s1,c2,s2 | P0..P3]
    __shared__ __align__(16) float Ks[16];

    int n = blockIdx.x * blockDim.x + threadIdx.x;   // patch index (exact grid)
    int b = n / NPATCH;
    int p = n - b * NPATCH;
    int r = p / 14;
    int c = p - r * 14;

    // Issue input loads before the barrier (overlap with thread-0 init).
    const float* img = x + b * 784 + (2 * r) * 28 + 2 * c;
    float2 top = *reinterpret_cast<const float2*>(img);
    float2 bot = *reinterpret_cast<const float2*>(img + 28);

    if (threadIdx.x == 0) {
        float c0, s0, c1, s1, c2, s2, c3, s3;
        __sincosf(params[4], &s0, &c0);
        __sincosf(params[5], &s1, &c1);
        __sincosf(params[6], &s2, &c2);
        __sincosf(params[7], &s3, &c3);
        Ks[0]  = c0 * c1;  Ks[1]  = s0 * s1;
        Ks[2]  = c0 * s1;  Ks[3]  = s0 * c1;
        Ks[4]  = c2 * c3;  Ks[5]  = s2 * s3;
        Ks[6]  = c2 * s3;  Ks[7]  = s2 * c3;
        Ks[8]  = c1;       Ks[9]  = s1;
        Ks[10] = c2;       Ks[11] = s2;
        Ks[12] = params[0]; Ks[13] = params[1];
        Ks[14] = params[2]; Ks[15] = params[3];
    }
    __syncthreads();

    const float4* Kv = reinterpret_cast<const float4*>(Ks);
    float4 KA = Kv[0];   // c01, s01, c0s1, s0c1
    float4 KB = Kv[1];   // c23, s23, c2s3, s2c3
    float4 KC = Kv[2];   // c1, s1, c2, s2
    float4 KP = Kv[3];   // P0..P3

    // Full angles a_v = x_v + params[0][v]; z = cos a, xs = sin a.
    float z0, x0, z1, x1, z2, x2, z3, x3;
    __sincosf(top.x + KP.x, &x0, &z0);
    __sincosf(top.y + KP.y, &x1, &z1);
    __sincosf(bot.x + KP.z, &x2, &z2);
    __sincosf(bot.y + KP.w, &x3, &z3);

    // Shared pair products.
    float zz01 = z0 * z1, zz02 = z0 * z2, zz03 = z0 * z3;
    float zz13 = z1 * z3, zz23 = z2 * z3;
    float xx01 = x0 * x1, xx02 = x0 * x2, xx03 = x0 * x3;
    float xx12 = x1 * x2, xx13 = x1 * x3, xx23 = x2 * x3;
    float zx23 = z2 * x3;

    // E[Z_0] = c1*( c23*(zz01*z3) - c2s3*(xx01*zx23) )
    //        - s1*( c23*(xx12*z3) + s23*x0 )
    float g1 = fmaf(-KB.z, xx01 * zx23, KB.x * (zz01 * z3));
    float g2 = fmaf( KB.y, x0,          KB.x * (xx12 * z3));
    float e0 = fmaf(-KC.y, g2, KC.x * g1);

    // E[Z_1] = c01*(z0*zz23) + s01*xx02
    float e1 = fmaf(KA.y, xx02, KA.x * (z0 * zz23));

    // E[Z_2] = c2*( c01*zz13 - c0s1*(xx12*zz03) - s0c1*(xx01*z2) )
    //        - s2*( s01*xx03 )
    float i2 = KA.x * zz13;
    i2 = fmaf(-KA.z, xx12 * zz03, i2);
    i2 = fmaf(-KA.w, xx01 * z2,   i2);
    float e2 = fmaf(-KC.w, KA.y * xx03, KC.z * i2);

    // E[Z_3] = c01*( c23*zz02 - s2c3*(z1*xx23) )
    //        + s01*( c23*(xx02*z3) + s23*x1 )
    //        + s0c1*( c2s3*zx23 - s23*(zz01*x2) )
    //        + c0s1*( s2c3*(z0*xx13) - s23*((zz13*z2)*x0) )
    float h1 = fmaf(-KB.w, z1 * xx23,        KB.x * zz02);
    float h2 = fmaf( KB.y, x1,               KB.x * (xx02 * z3));
    float h3 = fmaf(-KB.y, zz01 * x2,        KB.z * zx23);
    float h4 = fmaf(-KB.y, (zz13 * z2) * x0, KB.w * (z0 * xx13));
    float e3 = KA.x * h1;
    e3 = fmaf(KA.y, h2, e3);
    e3 = fmaf(KA.w, h3, e3);
    e3 = fmaf(KA.z, h4, e3);

    float4 o;
    o.x = e0; o.y = e1; o.z = e2; o.w = e3;
    reinterpret_cast<float4*>(out)[n] = o;
}

extern "C" void kernel_launch(void* const* d_in, const int* in_sizes, int n_in,
                              void* d_out, int out_size)
{
    const float* x      = (const float*)d_in[0];   // (8192,1,28,28) float32
    const float* params = (const float*)d_in[1];   // (2,4) float32
    float* out          = (float*)d_out;           // (8192, 784) float32

    (void)in_sizes; (void)n_in; (void)out_size;

    const int threads = 128;
    const int blocks  = NTOT / threads;            // 12544, exact
    quanv12_kernel<<<blocks, threads>>>(x, params, out);
}